// round 14
// baseline (speedup 1.0000x reference)
#include <cuda_runtime.h>
#include <cuda_bf16.h>
#include <cuda_fp16.h>
#include <math.h>
#include <stdint.h>

#define BB 4
#define SS 2048
#define HH 1024
#define NHH 16
#define HD 64
#define MM (BB*SS)   // 8192
#define LOG2E 1.4426950408889634f
#define SMAX 8.0f    // static softmax shift (log2 domain)

// ---------------- scratch (no allocation allowed) ----------------
__device__ float g_h[MM*HH];
__device__ __half g_x16[MM*HH];
__device__ __half g_q16[MM*HH];
__device__ __half g_k16[MM*HH];
__device__ __half g_v16[MM*HH];
__device__ __half g_c16[MM*HH];
__device__ __half g_wq16[HH*HH];
__device__ __half g_wk16[HH*HH];
__device__ __half g_wv16[HH*HH];
__device__ __half g_wo16[HH*HH];

// ================= PTX helpers (baseline ISA: sm_80 features only) =================
__device__ __forceinline__ uint32_t smem_u32(const void* p) {
    uint32_t a;
    asm("{ .reg .u64 t; cvta.to.shared.u64 t, %1; cvt.u32.u64 %0, t; }" : "=r"(a) : "l"(p));
    return a;
}

#define CP_ASYNC16(dst, src) \
    asm volatile("cp.async.cg.shared.global [%0], [%1], 16;" :: "r"(dst), "l"(src) : "memory")
#define CP_ASYNC4(dst, src) \
    asm volatile("cp.async.ca.shared.global [%0], [%1], 4;" :: "r"(dst), "l"(src) : "memory")
#define CP_COMMIT() asm volatile("cp.async.commit_group;" ::: "memory")
#define CP_WAIT2()  asm volatile("cp.async.wait_group 2;" ::: "memory")
#define CP_WAIT1()  asm volatile("cp.async.wait_group 1;" ::: "memory")
#define CP_WAIT0()  asm volatile("cp.async.wait_group 0;" ::: "memory")

#define LDSM4(r0, r1, r2, r3, addr) \
    asm volatile("ldmatrix.sync.aligned.m8n8.x4.shared.b16 {%0,%1,%2,%3}, [%4];" \
        : "=r"(r0), "=r"(r1), "=r"(r2), "=r"(r3) : "r"(addr))
#define LDSM4T(r0, r1, r2, r3, addr) \
    asm volatile("ldmatrix.sync.aligned.m8n8.x4.trans.shared.b16 {%0,%1,%2,%3}, [%4];" \
        : "=r"(r0), "=r"(r1), "=r"(r2), "=r"(r3) : "r"(addr))

#define MMA16816H(d, a, b) \
    asm volatile("mma.sync.aligned.m16n8k16.row.col.f32.f16.f16.f32 " \
        "{%0,%1,%2,%3}, {%4,%5,%6,%7}, {%8,%9}, {%0,%1,%2,%3};" \
        : "+f"((d)[0]), "+f"((d)[1]), "+f"((d)[2]), "+f"((d)[3]) \
        : "r"((a)[0]), "r"((a)[1]), "r"((a)[2]), "r"((a)[3]), "r"((b)[0]), "r"((b)[1]))

__device__ __forceinline__ uint32_t h2_u32(__half2 v) { return *(uint32_t*)&v; }

// ================= cast fp32 -> fp16 (all 5 tensors, one launch) =================
__device__ __forceinline__ void cast_body(const float* __restrict__ in,
                                          __half* __restrict__ out, int i)
{
    float4 v = ((const float4*)in)[i];
    ((uint2*)out)[i] = make_uint2(h2_u32(__float22half2_rn(make_float2(v.x, v.y))),
                                  h2_u32(__float22half2_rn(make_float2(v.z, v.w))));
}

struct CastAll {
    const float* in[5];
    __half* out[5];
    int n4[5];
};

__global__ __launch_bounds__(256)
void castall_kernel(CastAll P)
{
    const int z = blockIdx.y;
    const int i = blockIdx.x * blockDim.x + threadIdx.x;
    if (i >= P.n4[z]) return;
    cast_body(P.in[z], P.out[z], i);
}

// ================= fp16 GEMM: A via smem, B fragments direct from gmem/L2 =================
// CTA 128x128, warp tile 64x32 (2x4 warp grid), K-chunk 64, 2-stage A ring.
// B (weights, 2MB, L2-resident): b-frag thread mapping n = l>>2, k = (l&3)*2
// -> two coalesced 32-bit LDGs per fragment. No B smem staging at all.
#define GNCHUNK 16           // 1024 / 64
#define GROWB 144            // 128B data + 16B pad
#define GMATB (128 * GROWB)  // 18432 (A tile only)
#define GSMEM (2 * GMATB)    // 36864

__device__ __forceinline__
void gemm_body(const __half* __restrict__ A16, const __half* __restrict__ B16,
               const float* __restrict__ bias, const float* __restrict__ resid,
               float* __restrict__ Cf, __half* __restrict__ O16,
               float oscale, uint32_t sbase)
{
    const int tid = threadIdx.x;
    const int wid = tid >> 5, lane = tid & 31;
    const int warp_m = wid & 1, warp_n = wid >> 1;
    const int r0 = blockIdx.y * 128, c0 = blockIdx.x * 128;

    float acc[4][4][4];
#pragma unroll
    for (int i = 0; i < 4; i++)
#pragma unroll
        for (int j = 0; j < 4; j++)
#pragma unroll
            for (int q = 0; q < 4; q++) acc[i][j][q] = 0.f;

    // per-thread base pointer for B fragment loads:
    // row n = c0 + warp_n*32 + nb*8 + (lane>>2); col k = (lane&3)*2 within each k16 step
    const __half* bbase = B16 + (long)(c0 + warp_n * 32 + (lane >> 2)) * HH + (lane & 3) * 2;

#define G_LOAD_A(c, s) do { \
    const uint32_t st = sbase + (s) * GMATB; \
    const long ka = (long)(c) * 64; \
    _Pragma("unroll") \
    for (int i_ = 0; i_ < 4; i_++) { \
        int idx = tid + 256 * i_; \
        int row = idx >> 3, u = idx & 7; \
        CP_ASYNC16(st + row * GROWB + u * 16, A16 + (long)(r0 + row) * HH + ka + u * 8); \
    } \
    CP_COMMIT(); \
} while (0)

    // load b-frags for one k16 step (ks within chunk c): 4 n-blocks x 2 regs
#define G_LOAD_B(c, ks, breg) do { \
    const long ko = (long)(c) * 64 + (ks) * 16; \
    _Pragma("unroll") \
    for (int nb = 0; nb < 4; nb++) { \
        const __half* wp = bbase + (long)nb * 8 * HH + ko; \
        (breg)[nb][0] = *(const uint32_t*)wp; \
        (breg)[nb][1] = *(const uint32_t*)(wp + 8); \
    } \
} while (0)

    G_LOAD_A(0, 0);

    const int sub = lane >> 3, lr = lane & 7;

#pragma unroll 1
    for (int c = 0; c < GNCHUNK; c++) {
        if (c + 1 < GNCHUNK) {
            G_LOAD_A(c + 1, (c + 1) & 1);
            CP_WAIT1();
        } else {
            CP_WAIT0();
        }
        __syncthreads();

        const uint32_t a_b = sbase + (c & 1) * GMATB;

        uint32_t breg[2][4][2];
        G_LOAD_B(c, 0, breg[0]);

#pragma unroll
        for (int ks = 0; ks < 4; ks++) {
            if (ks < 3) G_LOAD_B(c, ks + 1, breg[(ks + 1) & 1]);
            uint32_t af[4][4];
            const int aunit = ks * 2 + (sub >> 1);
#pragma unroll
            for (int mf = 0; mf < 4; mf++) {
                const int arow = warp_m * 64 + mf * 16 + (sub & 1) * 8 + lr;
                LDSM4(af[mf][0], af[mf][1], af[mf][2], af[mf][3],
                      a_b + arow * GROWB + aunit * 16);
            }
#pragma unroll
            for (int mf = 0; mf < 4; mf++)
#pragma unroll
                for (int nf = 0; nf < 4; nf++)
                    MMA16816H(acc[mf][nf], af[mf], breg[ks & 1][nf]);
        }
        __syncthreads();
    }

    const int g = lane >> 2, t4 = lane & 3;
#pragma unroll
    for (int mf = 0; mf < 4; mf++) {
#pragma unroll
        for (int nf = 0; nf < 4; nf++) {
            const int col = c0 + warp_n * 32 + nf * 8 + 2 * t4;
            const int rowA = r0 + warp_m * 64 + mf * 16 + g;
            const int rowB = rowA + 8;
            float v0 = acc[mf][nf][0] + bias[col];
            float v1 = acc[mf][nf][1] + bias[col + 1];
            float v2 = acc[mf][nf][2] + bias[col];
            float v3 = acc[mf][nf][3] + bias[col + 1];
            if (O16) {
                v0 *= oscale; v1 *= oscale; v2 *= oscale; v3 *= oscale;
                *(uint32_t*)&O16[(long)rowA * HH + col] =
                    h2_u32(__float22half2_rn(make_float2(v0, v1)));
                *(uint32_t*)&O16[(long)rowB * HH + col] =
                    h2_u32(__float22half2_rn(make_float2(v2, v3)));
            } else {
                if (resid) {
                    const float2 ra = *(const float2*)&resid[(long)rowA * HH + col];
                    const float2 rb = *(const float2*)&resid[(long)rowB * HH + col];
                    v0 += ra.x; v1 += ra.y; v2 += rb.x; v3 += rb.y;
                }
                *(float2*)&Cf[(long)rowA * HH + col] = make_float2(v0, v1);
                *(float2*)&Cf[(long)rowB * HH + col] = make_float2(v2, v3);
            }
        }
    }
}

struct QKVParams {
    const __half* w[3];
    const float* bias[3];
    __half* o[3];
};

__global__ __launch_bounds__(256, 2)
void gemm_qkv(const __half* __restrict__ A16, QKVParams P)
{
    extern __shared__ char smem[];
    const int z = blockIdx.z;
    gemm_body(A16, P.w[z], P.bias[z], nullptr, nullptr, P.o[z],
              (z == 0) ? (0.125f * LOG2E) : 1.0f, smem_u32(smem));
}

__global__ __launch_bounds__(256, 2)
void gemm_out(const __half* __restrict__ A16, const __half* __restrict__ B16,
              const float* __restrict__ bias, const float* __restrict__ resid,
              float* __restrict__ Cf)
{
    extern __shared__ char smem[];
    gemm_body(A16, B16, bias, resid, Cf, nullptr, 1.0f, smem_u32(smem));
}

// ================= fp16 flash attention (16-row warp tiles, 2 CTA/SM, static-max) =================
#define NT (SS / 64)            // 32 tiles
#define AQTB 16384              // Q tile: 128 rows x 128B
#define AKTB 8192               // 64 rows x 128B
#define AKVSTG (2 * AKTB)       // K, V per stage
#define ASMEM (AQTB + 3*AKVSTG + 3*256 + 256)   // 66560

__device__ __forceinline__ uint32_t swz(int row, int unit) {
    return (uint32_t)(row * 128 + ((unit ^ (row & 7)) * 16));
}

__global__ __launch_bounds__(256, 2)
void attn_mma(const __half* __restrict__ Q16, const __half* __restrict__ K16,
              const __half* __restrict__ V16, const float* __restrict__ mask,
              __half* __restrict__ C16)
{
    extern __shared__ char smem[];
    const uint32_t sb = smem_u32(smem);
    const int tid = threadIdx.x, wid = tid >> 5, lane = tid & 31;
    const int sub = lane >> 3, lr = lane & 7;
    const int b = blockIdx.z, h = blockIdx.y;
    const int q0 = blockIdx.x * 128;
    const long rowb = (long)b * SS;
    const int hc = h * 64;

    const uint32_t s_q = sb;
    const uint32_t s_kv = sb + AQTB;
    const uint32_t s_mk = sb + AQTB + 3 * AKVSTG;
    const char* mkp = smem + AQTB + 3 * AKVSTG;

    // ---- load Q tile (group 0) ----
#pragma unroll
    for (int i = 0; i < 4; i++) {
        int idx = tid + 256 * i;
        int row = idx >> 3, u = idx & 7;
        CP_ASYNC16(s_q + swz(row, u), Q16 + (rowb + q0 + row) * HH + hc + u * 8);
    }
    CP_COMMIT();

#define A_LOAD_KV(t, st) do { \
    const uint32_t kb_ = s_kv + (st) * AKVSTG; \
    const long k0_ = (long)(t) * 64; \
    _Pragma("unroll") \
    for (int i_ = 0; i_ < 2; i_++) { \
        int idx = tid + 256 * i_; \
        int row = idx >> 3, u = idx & 7; \
        long go = (rowb + k0_ + row) * HH + hc + u * 8; \
        uint32_t so = swz(row, u); \
        CP_ASYNC16(kb_ + so, K16 + go); \
        CP_ASYNC16(kb_ + AKTB + so, V16 + go); \
    } \
    if (tid < 64) CP_ASYNC4(s_mk + (st) * 256 + tid * 4, mask + rowb + k0_ + tid); \
    CP_COMMIT(); \
} while (0)

    A_LOAD_KV(0, 0);   // group 1
    A_LOAD_KV(1, 1);   // group 2

    // ---- hoist Q fragments (loop-invariant across all KV tiles) ----
    CP_WAIT2();        // Q (group 0) complete
    __syncthreads();
    uint32_t qf[4][4];
    {
        const int arow = wid * 16 + (sub & 1) * 8 + lr;
#pragma unroll
        for (int ks = 0; ks < 4; ks++)
            LDSM4(qf[ks][0], qf[ks][1], qf[ks][2], qf[ks][3],
                  s_q + swz(arow, ks * 2 + (sub >> 1)));
    }

    float o[8][4];
#pragma unroll
    for (int i = 0; i < 8; i++)
#pragma unroll
        for (int j = 0; j < 4; j++) o[i][j] = 0.f;
    float osum[4] = {0.f, 0.f, 0.f, 0.f};   // row-sum (l) via ones-MMA; never rescaled
    uint32_t ones2[2];
    ones2[0] = 0x3C003C00u; ones2[1] = 0x3C003C00u;  // fp16 1.0 x4

    const int t2 = (lane & 3) * 2;
    int st = 0;       // stage of tile t
    int st2 = 2;      // stage of tile t+2

#pragma unroll 1
    for (int t = 0; t < NT; t++) {
        if (t + 2 < NT) CP_WAIT1(); else CP_WAIT0();
        __syncthreads();
        if (t + 2 < NT) A_LOAD_KV(t + 2, st2);
        const uint32_t kb = s_kv + st * AKVSTG;

        // ---- S_log2 = (Q*scale*log2e) @ K^T (fp16): 128x64 ----
        float s[8][4];
#pragma unroll
        for (int i = 0; i < 8; i++)
#pragma unroll
            for (int j = 0; j < 4; j++) s[i][j] = 0.f;

#pragma unroll
        for (int ks = 0; ks < 4; ks++) {
#pragma unroll
            for (int np = 0; np < 4; np++) {
                uint32_t bh[4];
                const int brow = np * 16 + (sub >> 1) * 8 + lr;
                LDSM4(bh[0], bh[1], bh[2], bh[3], kb + swz(brow, ks * 2 + (sub & 1)));
                MMA16816H(s[np*2],   qf[ks], &bh[0]);
                MMA16816H(s[np*2+1], qf[ks], &bh[2]);
            }
        }

        // ---- P = exp2(s + mask*log2e - SMAX) in fp16x2; no max reduction ----
        uint32_t ph[4][4];
#pragma unroll
        for (int ks = 0; ks < 4; ks++) {
            const float2 mvA = *(const float2*)(mkp + st * 256 + ((2*ks)   * 8 + t2) * 4);
            const float2 mvB = *(const float2*)(mkp + st * 256 + ((2*ks+1) * 8 + t2) * 4);
            const float cA0 = fmaf(mvA.x, LOG2E, -SMAX), cA1 = fmaf(mvA.y, LOG2E, -SMAX);
            const float cB0 = fmaf(mvB.x, LOG2E, -SMAX), cB1 = fmaf(mvB.y, LOG2E, -SMAX);
            ph[ks][0] = h2_u32(h2exp2(__floats2half2_rn(s[2*ks][0]   + cA0, s[2*ks][1]   + cA1)));
            ph[ks][1] = h2_u32(h2exp2(__floats2half2_rn(s[2*ks][2]   + cA0, s[2*ks][3]   + cA1)));
            ph[ks][2] = h2_u32(h2exp2(__floats2half2_rn(s[2*ks+1][0] + cB0, s[2*ks+1][1] + cB1)));
            ph[ks][3] = h2_u32(h2exp2(__floats2half2_rn(s[2*ks+1][2] + cB0, s[2*ks+1][3] + cB1)));
        }

        // ---- O += P @ V ; l += P @ 1 (both on tensor pipe, no rescale) ----
        const uint32_t vb = kb + AKTB;
#pragma unroll
        for (int ks = 0; ks < 4; ks++) {
            MMA16816H(osum, ph[ks], ones2);
#pragma unroll
            for (int np = 0; np < 4; np++) {
                uint32_t bh[4];
                const int vrow = ks * 16 + (sub & 1) * 8 + lr;
                LDSM4T(bh[0], bh[1], bh[2], bh[3], vb + swz(vrow, np * 2 + (sub >> 1)));
                MMA16816H(o[np*2],   ph[ks], &bh[0]);
                MMA16816H(o[np*2+1], ph[ks], &bh[2]);
            }
        }

        st = (st == 2) ? 0 : st + 1;
        st2 = (st2 == 2) ? 0 : st2 + 1;
    }

    // ---- epilogue: ctx = o / l -> fp16 ----
    const float i0 = 1.f / osum[0], i1 = 1.f / osum[2];
    const int rA = q0 + wid * 16 + (lane >> 2);
    const long baseA = (rowb + rA) * HH + hc;
    const long baseB = baseA + 8LL * HH;
#pragma unroll
    for (int np = 0; np < 8; np++) {
        const int col = np * 8 + t2;
        *(uint32_t*)&C16[baseA + col] =
            h2_u32(__float22half2_rn(make_float2(o[np][0] * i0, o[np][1] * i0)));
        *(uint32_t*)&C16[baseB + col] =
            h2_u32(__float22half2_rn(make_float2(o[np][2] * i1, o[np][3] * i1)));
    }
}

// ================= LayerNorm =================
__global__ __launch_bounds__(256)
void ln_kernel(const float* __restrict__ Hin, const float* __restrict__ w,
               const float* __restrict__ bv, float* __restrict__ out)
{
    __shared__ float red[2][8];
    int row = blockIdx.x;
    int tid = threadIdx.x;
    const float4* xp = (const float4*)(Hin + (size_t)row * HH);
    float4 v = xp[tid];
    float s = v.x + v.y + v.z + v.w;
    float sq = v.x * v.x + v.y * v.y + v.z * v.z + v.w * v.w;
#pragma unroll
    for (int m = 16; m >= 1; m >>= 1) {
        s += __shfl_xor_sync(0xffffffffu, s, m);
        sq += __shfl_xor_sync(0xffffffffu, sq, m);
    }
    int wid = tid >> 5, lid = tid & 31;
    if (lid == 0) { red[0][wid] = s; red[1][wid] = sq; }
    __syncthreads();
    if (wid == 0) {
        float a = (lid < 8) ? red[0][lid] : 0.f;
        float b = (lid < 8) ? red[1][lid] : 0.f;
#pragma unroll
        for (int m = 4; m >= 1; m >>= 1) {
            a += __shfl_xor_sync(0xffffffffu, a, m);
            b += __shfl_xor_sync(0xffffffffu, b, m);
        }
        if (lid == 0) { red[0][0] = a; red[1][0] = b; }
    }
    __syncthreads();
    float mean = red[0][0] * (1.f / HH);
    float var = red[1][0] * (1.f / HH) - mean * mean;
    float rstd = rsqrtf(var + 1e-12f);

    const float4 wv = ((const float4*)w)[tid];
    const float4 bb = ((const float4*)bv)[tid];
    float4 o;
    o.x = wv.x * (v.x - mean) * rstd + bb.x;
    o.y = wv.y * (v.y - mean) * rstd + bb.y;
    o.z = wv.z * (v.z - mean) * rstd + bb.z;
    o.w = wv.w * (v.w - mean) * rstd + bb.w;
    ((float4*)(out + (size_t)row * HH))[tid] = o;
}

// ================= launch =================
extern "C" void kernel_launch(void* const* d_in, const int* in_sizes, int n_in,
                              void* d_out, int out_size)
{
    const float* x    = (const float*)d_in[0];
    const float* mask = (const float*)d_in[1];
    const float* Wq   = (const float*)d_in[2];
    const float* bq   = (const float*)d_in[3];
    const float* Wk   = (const float*)d_in[4];
    const float* bk   = (const float*)d_in[5];
    const float* Wv   = (const float*)d_in[6];
    const float* bv   = (const float*)d_in[7];
    const float* Wo   = (const float*)d_in[8];
    const float* bo   = (const float*)d_in[9];
    const float* lnw  = (const float*)d_in[10];
    const float* lnb  = (const float*)d_in[11];
    float* out = (float*)d_out;

    float* hbuf;
    cudaGetSymbolAddress((void**)&hbuf, g_h);
    __half *x16, *q16, *k16, *v16, *c16, *wq16, *wk16, *wv16, *wo16;
    cudaGetSymbolAddress((void**)&x16, g_x16);
    cudaGetSymbolAddress((void**)&q16, g_q16);
    cudaGetSymbolAddress((void**)&k16, g_k16);
    cudaGetSymbolAddress((void**)&v16, g_v16);
    cudaGetSymbolAddress((void**)&c16, g_c16);
    cudaGetSymbolAddress((void**)&wq16, g_wq16);
    cudaGetSymbolAddress((void**)&wk16, g_wk16);
    cudaGetSymbolAddress((void**)&wv16, g_wv16);
    cudaGetSymbolAddress((void**)&wo16, g_wo16);

    cudaFuncSetAttribute(gemm_qkv, cudaFuncAttributeMaxDynamicSharedMemorySize, GSMEM);
    cudaFuncSetAttribute(gemm_out, cudaFuncAttributeMaxDynamicSharedMemorySize, GSMEM);
    cudaFuncSetAttribute(attn_mma, cudaFuncAttributeMaxDynamicSharedMemorySize, ASMEM);

    const int n4x = MM * HH / 4;
    const int n4w = HH * HH / 4;

    // one fused cast launch: x + 4 weight matrices
    CastAll CA;
    CA.in[0] = x;  CA.out[0] = x16;  CA.n4[0] = n4x;
    CA.in[1] = Wq; CA.out[1] = wq16; CA.n4[1] = n4w;
    CA.in[2] = Wk; CA.out[2] = wk16; CA.n4[2] = n4w;
    CA.in[3] = Wv; CA.out[3] = wv16; CA.n4[3] = n4w;
    CA.in[4] = Wo; CA.out[4] = wo16; CA.n4[4] = n4w;
    dim3 cgrid(n4x / 256, 5);
    castall_kernel<<<cgrid, 256>>>(CA);

    // fused QKV projections (Q pre-scaled by log2e/8)
    QKVParams P;
    P.w[0] = wq16; P.bias[0] = bq; P.o[0] = q16;
    P.w[1] = wk16; P.bias[1] = bk; P.o[1] = k16;
    P.w[2] = wv16; P.bias[2] = bv; P.o[2] = v16;
    dim3 qkvgrid(HH / 128, MM / 128, 3);   // (8, 64, 3)
    gemm_qkv<<<qkvgrid, 256, GSMEM>>>(x16, P);

    // fp16 flash attention (static-max) -> ctx fp16
    dim3 agrid(SS / 128, NHH, BB);
    attn_mma<<<agrid, 256, ASMEM>>>(q16, k16, v16, mask, c16);

    // output projection + residual -> fp32 h
    dim3 ggrid(HH / 128, MM / 128);        // (8, 64)
    gemm_out<<<ggrid, 256, GSMEM>>>(c16, wo16, bo, x, hbuf);

    ln_kernel<<<MM, 256>>>(hbuf, lnw, lnb, out);
}

// round 15
// speedup vs baseline: 1.2939x; 1.2939x over previous
#include <cuda_runtime.h>
#include <cuda_bf16.h>
#include <cuda_fp16.h>
#include <math.h>
#include <stdint.h>

#define BB 4
#define SS 2048
#define HH 1024
#define NHH 16
#define HD 64
#define MM (BB*SS)   // 8192
#define LOG2E 1.4426950408889634f
#define SMAX 8.0f    // static softmax shift (log2 domain)

// ---------------- scratch (no allocation allowed) ----------------
__device__ float g_h[MM*HH];
__device__ __half g_x16[MM*HH];
__device__ __half g_q16[MM*HH];
__device__ __half g_k16[MM*HH];
__device__ __half g_v16[MM*HH];
__device__ __half g_c16[MM*HH];
__device__ __half g_wq16[HH*HH];
__device__ __half g_wk16[HH*HH];
__device__ __half g_wv16[HH*HH];
__device__ __half g_wo16[HH*HH];

// ================= PTX helpers (baseline ISA: sm_80 features only) =================
__device__ __forceinline__ uint32_t smem_u32(const void* p) {
    uint32_t a;
    asm("{ .reg .u64 t; cvta.to.shared.u64 t, %1; cvt.u32.u64 %0, t; }" : "=r"(a) : "l"(p));
    return a;
}

#define CP_ASYNC16(dst, src) \
    asm volatile("cp.async.cg.shared.global [%0], [%1], 16;" :: "r"(dst), "l"(src) : "memory")
#define CP_ASYNC4(dst, src) \
    asm volatile("cp.async.ca.shared.global [%0], [%1], 4;" :: "r"(dst), "l"(src) : "memory")
#define CP_COMMIT() asm volatile("cp.async.commit_group;" ::: "memory")
#define CP_WAIT2()  asm volatile("cp.async.wait_group 2;" ::: "memory")
#define CP_WAIT1()  asm volatile("cp.async.wait_group 1;" ::: "memory")
#define CP_WAIT0()  asm volatile("cp.async.wait_group 0;" ::: "memory")

#define LDSM4(r0, r1, r2, r3, addr) \
    asm volatile("ldmatrix.sync.aligned.m8n8.x4.shared.b16 {%0,%1,%2,%3}, [%4];" \
        : "=r"(r0), "=r"(r1), "=r"(r2), "=r"(r3) : "r"(addr))
#define LDSM4T(r0, r1, r2, r3, addr) \
    asm volatile("ldmatrix.sync.aligned.m8n8.x4.trans.shared.b16 {%0,%1,%2,%3}, [%4];" \
        : "=r"(r0), "=r"(r1), "=r"(r2), "=r"(r3) : "r"(addr))

#define MMA16816H(d, a, b) \
    asm volatile("mma.sync.aligned.m16n8k16.row.col.f32.f16.f16.f32 " \
        "{%0,%1,%2,%3}, {%4,%5,%6,%7}, {%8,%9}, {%0,%1,%2,%3};" \
        : "+f"((d)[0]), "+f"((d)[1]), "+f"((d)[2]), "+f"((d)[3]) \
        : "r"((a)[0]), "r"((a)[1]), "r"((a)[2]), "r"((a)[3]), "r"((b)[0]), "r"((b)[1]))

__device__ __forceinline__ uint32_t h2_u32(__half2 v) { return *(uint32_t*)&v; }

// ================= cast fp32 -> fp16 (all 5 tensors, one launch) =================
__device__ __forceinline__ void cast_body(const float* __restrict__ in,
                                          __half* __restrict__ out, int i)
{
    float4 v = ((const float4*)in)[i];
    ((uint2*)out)[i] = make_uint2(h2_u32(__float22half2_rn(make_float2(v.x, v.y))),
                                  h2_u32(__float22half2_rn(make_float2(v.z, v.w))));
}

struct CastAll {
    const float* in[5];
    __half* out[5];
    int n4[5];
};

__global__ __launch_bounds__(256)
void castall_kernel(CastAll P)
{
    const int z = blockIdx.y;
    const int i = blockIdx.x * blockDim.x + threadIdx.x;
    if (i >= P.n4[z]) return;
    cast_body(P.in[z], P.out[z], i);
}

// ================= fp16 GEMM (R10 champion form): C = A @ W^T + bias =================
// CTA 128x128, warp tile 64x32, K-chunk 64, 2-stage smem double buffer.
#define GNCHUNK 16           // 1024 / 64
#define GROWB 144            // 128B data + 16B pad
#define GMATB (128 * GROWB)  // 18432
#define GSTG (2 * GMATB)     // 36864 (A, B)
#define GSMEM (2 * GSTG)     // 73728

__device__ __forceinline__
void gemm_body(const __half* __restrict__ A16, const __half* __restrict__ B16,
               const float* __restrict__ bias, const float* __restrict__ resid,
               float* __restrict__ Cf, __half* __restrict__ O16,
               float oscale, uint32_t sbase)
{
    const int tid = threadIdx.x;
    const int wid = tid >> 5, lane = tid & 31;
    const int warp_m = wid & 1, warp_n = wid >> 1;
    const int r0 = blockIdx.y * 128, c0 = blockIdx.x * 128;

    float acc[4][4][4];
#pragma unroll
    for (int i = 0; i < 4; i++)
#pragma unroll
        for (int j = 0; j < 4; j++)
#pragma unroll
            for (int q = 0; q < 4; q++) acc[i][j][q] = 0.f;

#define G_LOAD_CHUNK(c, s) do { \
    const uint32_t st = sbase + (s) * GSTG; \
    const long ka = (long)(c) * 64; \
    _Pragma("unroll") \
    for (int i_ = 0; i_ < 4; i_++) { \
        int idx = tid + 256 * i_; \
        int row = idx >> 3, u = idx & 7; \
        CP_ASYNC16(st + row * GROWB + u * 16, A16 + (long)(r0 + row) * HH + ka + u * 8); \
        CP_ASYNC16(st + GMATB + row * GROWB + u * 16, B16 + (long)(c0 + row) * HH + ka + u * 8); \
    } \
    CP_COMMIT(); \
} while (0)

    G_LOAD_CHUNK(0, 0);

    const int sub = lane >> 3, lr = lane & 7;

#pragma unroll 1
    for (int c = 0; c < GNCHUNK; c++) {
        if (c + 1 < GNCHUNK) {
            G_LOAD_CHUNK(c + 1, (c + 1) & 1);
            CP_WAIT1();
        } else {
            CP_WAIT0();
        }
        __syncthreads();

        const uint32_t a_b = sbase + (c & 1) * GSTG;
        const uint32_t b_b = a_b + GMATB;

#pragma unroll
        for (int ks = 0; ks < 4; ks++) {
            uint32_t af[4][4], bf[2][4];
            const int aunit = ks * 2 + (sub >> 1);
#pragma unroll
            for (int mf = 0; mf < 4; mf++) {
                const int arow = warp_m * 64 + mf * 16 + (sub & 1) * 8 + lr;
                LDSM4(af[mf][0], af[mf][1], af[mf][2], af[mf][3],
                      a_b + arow * GROWB + aunit * 16);
            }
            const int bunit = ks * 2 + (sub & 1);
#pragma unroll
            for (int pr = 0; pr < 2; pr++) {
                const int brow = warp_n * 32 + pr * 16 + (sub >> 1) * 8 + lr;
                LDSM4(bf[pr][0], bf[pr][1], bf[pr][2], bf[pr][3],
                      b_b + brow * GROWB + bunit * 16);
            }
#pragma unroll
            for (int mf = 0; mf < 4; mf++)
#pragma unroll
                for (int nf = 0; nf < 4; nf++)
                    MMA16816H(acc[mf][nf], af[mf], &bf[nf >> 1][(nf & 1) * 2]);
        }
        __syncthreads();
    }

    const int g = lane >> 2, t4 = lane & 3;
#pragma unroll
    for (int mf = 0; mf < 4; mf++) {
#pragma unroll
        for (int nf = 0; nf < 4; nf++) {
            const int col = c0 + warp_n * 32 + nf * 8 + 2 * t4;
            const int rowA = r0 + warp_m * 64 + mf * 16 + g;
            const int rowB = rowA + 8;
            float v0 = acc[mf][nf][0] + bias[col];
            float v1 = acc[mf][nf][1] + bias[col + 1];
            float v2 = acc[mf][nf][2] + bias[col];
            float v3 = acc[mf][nf][3] + bias[col + 1];
            if (O16) {
                v0 *= oscale; v1 *= oscale; v2 *= oscale; v3 *= oscale;
                *(uint32_t*)&O16[(long)rowA * HH + col] =
                    h2_u32(__float22half2_rn(make_float2(v0, v1)));
                *(uint32_t*)&O16[(long)rowB * HH + col] =
                    h2_u32(__float22half2_rn(make_float2(v2, v3)));
            } else {
                if (resid) {
                    const float2 ra = *(const float2*)&resid[(long)rowA * HH + col];
                    const float2 rb = *(const float2*)&resid[(long)rowB * HH + col];
                    v0 += ra.x; v1 += ra.y; v2 += rb.x; v3 += rb.y;
                }
                *(float2*)&Cf[(long)rowA * HH + col] = make_float2(v0, v1);
                *(float2*)&Cf[(long)rowB * HH + col] = make_float2(v2, v3);
            }
        }
    }
}

struct QKVParams {
    const __half* w[3];
    const float* bias[3];
    __half* o[3];
};

__global__ __launch_bounds__(256, 2)
void gemm_qkv(const __half* __restrict__ A16, QKVParams P)
{
    extern __shared__ char smem[];
    const int z = blockIdx.z;
    gemm_body(A16, P.w[z], P.bias[z], nullptr, nullptr, P.o[z],
              (z == 0) ? (0.125f * LOG2E) : 1.0f, smem_u32(smem));
}

__global__ __launch_bounds__(256, 2)
void gemm_out(const __half* __restrict__ A16, const __half* __restrict__ B16,
              const float* __restrict__ bias, const float* __restrict__ resid,
              float* __restrict__ Cf)
{
    extern __shared__ char smem[];
    gemm_body(A16, B16, bias, resid, Cf, nullptr, 1.0f, smem_u32(smem));
}

// ================= fp16 flash attention (R10 champion: 16-row warp tiles, 2 CTA/SM) =================
#define NT (SS / 64)            // 32 tiles
#define AQTB 16384              // Q tile: 128 rows x 128B
#define AKTB 8192               // 64 rows x 128B
#define AKVSTG (2 * AKTB)       // K, V per stage
#define ASMEM (AQTB + 3*AKVSTG + 3*256 + 256)   // 66560

__device__ __forceinline__ uint32_t swz(int row, int unit) {
    return (uint32_t)(row * 128 + ((unit ^ (row & 7)) * 16));
}

__global__ __launch_bounds__(256, 2)
void attn_mma(const __half* __restrict__ Q16, const __half* __restrict__ K16,
              const __half* __restrict__ V16, const float* __restrict__ mask,
              __half* __restrict__ C16)
{
    extern __shared__ char smem[];
    const uint32_t sb = smem_u32(smem);
    const int tid = threadIdx.x, wid = tid >> 5, lane = tid & 31;
    const int sub = lane >> 3, lr = lane & 7;
    const int b = blockIdx.z, h = blockIdx.y;
    const int q0 = blockIdx.x * 128;
    const long rowb = (long)b * SS;
    const int hc = h * 64;

    const uint32_t s_q = sb;
    const uint32_t s_kv = sb + AQTB;
    const uint32_t s_mk = sb + AQTB + 3 * AKVSTG;
    const char* mkp = smem + AQTB + 3 * AKVSTG;

    // ---- load Q tile (group 0) ----
#pragma unroll
    for (int i = 0; i < 4; i++) {
        int idx = tid + 256 * i;
        int row = idx >> 3, u = idx & 7;
        CP_ASYNC16(s_q + swz(row, u), Q16 + (rowb + q0 + row) * HH + hc + u * 8);
    }
    CP_COMMIT();

#define A_LOAD_KV(t, st) do { \
    const uint32_t kb_ = s_kv + (st) * AKVSTG; \
    const long k0_ = (long)(t) * 64; \
    _Pragma("unroll") \
    for (int i_ = 0; i_ < 2; i_++) { \
        int idx = tid + 256 * i_; \
        int row = idx >> 3, u = idx & 7; \
        long go = (rowb + k0_ + row) * HH + hc + u * 8; \
        uint32_t so = swz(row, u); \
        CP_ASYNC16(kb_ + so, K16 + go); \
        CP_ASYNC16(kb_ + AKTB + so, V16 + go); \
    } \
    if (tid < 64) CP_ASYNC4(s_mk + (st) * 256 + tid * 4, mask + rowb + k0_ + tid); \
    CP_COMMIT(); \
} while (0)

    A_LOAD_KV(0, 0);   // group 1
    A_LOAD_KV(1, 1);   // group 2

    // ---- hoist Q fragments (loop-invariant across all KV tiles) ----
    CP_WAIT2();        // Q (group 0) complete
    __syncthreads();
    uint32_t qf[4][4];
    {
        const int arow = wid * 16 + (sub & 1) * 8 + lr;
#pragma unroll
        for (int ks = 0; ks < 4; ks++)
            LDSM4(qf[ks][0], qf[ks][1], qf[ks][2], qf[ks][3],
                  s_q + swz(arow, ks * 2 + (sub >> 1)));
    }

    float o[8][4];
#pragma unroll
    for (int i = 0; i < 8; i++)
#pragma unroll
        for (int j = 0; j < 4; j++) o[i][j] = 0.f;
    float osum[4] = {0.f, 0.f, 0.f, 0.f};   // row-sum (l) via ones-MMA; never rescaled
    uint32_t ones2[2];
    ones2[0] = 0x3C003C00u; ones2[1] = 0x3C003C00u;  // fp16 1.0 x4

    const int t2 = (lane & 3) * 2;
    int st = 0;       // stage of tile t
    int st2 = 2;      // stage of tile t+2

#pragma unroll 1
    for (int t = 0; t < NT; t++) {
        if (t + 2 < NT) CP_WAIT1(); else CP_WAIT0();
        __syncthreads();
        if (t + 2 < NT) A_LOAD_KV(t + 2, st2);
        const uint32_t kb = s_kv + st * AKVSTG;

        // ---- S_log2 = (Q*scale*log2e) @ K^T (fp16): 128x64 ----
        float s[8][4];
#pragma unroll
        for (int i = 0; i < 8; i++)
#pragma unroll
            for (int j = 0; j < 4; j++) s[i][j] = 0.f;

#pragma unroll
        for (int ks = 0; ks < 4; ks++) {
#pragma unroll
            for (int np = 0; np < 4; np++) {
                uint32_t bh[4];
                const int brow = np * 16 + (sub >> 1) * 8 + lr;
                LDSM4(bh[0], bh[1], bh[2], bh[3], kb + swz(brow, ks * 2 + (sub & 1)));
                MMA16816H(s[np*2],   qf[ks], &bh[0]);
                MMA16816H(s[np*2+1], qf[ks], &bh[2]);
            }
        }

        // ---- P = exp2(s + mask*log2e - SMAX) in fp16x2; no max reduction ----
        uint32_t ph[4][4];
#pragma unroll
        for (int ks = 0; ks < 4; ks++) {
            const float2 mvA = *(const float2*)(mkp + st * 256 + ((2*ks)   * 8 + t2) * 4);
            const float2 mvB = *(const float2*)(mkp + st * 256 + ((2*ks+1) * 8 + t2) * 4);
            const float cA0 = fmaf(mvA.x, LOG2E, -SMAX), cA1 = fmaf(mvA.y, LOG2E, -SMAX);
            const float cB0 = fmaf(mvB.x, LOG2E, -SMAX), cB1 = fmaf(mvB.y, LOG2E, -SMAX);
            ph[ks][0] = h2_u32(h2exp2(__floats2half2_rn(s[2*ks][0]   + cA0, s[2*ks][1]   + cA1)));
            ph[ks][1] = h2_u32(h2exp2(__floats2half2_rn(s[2*ks][2]   + cA0, s[2*ks][3]   + cA1)));
            ph[ks][2] = h2_u32(h2exp2(__floats2half2_rn(s[2*ks+1][0] + cB0, s[2*ks+1][1] + cB1)));
            ph[ks][3] = h2_u32(h2exp2(__floats2half2_rn(s[2*ks+1][2] + cB0, s[2*ks+1][3] + cB1)));
        }

        // ---- O += P @ V ; l += P @ 1 (both on tensor pipe, no rescale) ----
        const uint32_t vb = kb + AKTB;
#pragma unroll
        for (int ks = 0; ks < 4; ks++) {
            MMA16816H(osum, ph[ks], ones2);
#pragma unroll
            for (int np = 0; np < 4; np++) {
                uint32_t bh[4];
                const int vrow = ks * 16 + (sub & 1) * 8 + lr;
                LDSM4T(bh[0], bh[1], bh[2], bh[3], vb + swz(vrow, np * 2 + (sub >> 1)));
                MMA16816H(o[np*2],   ph[ks], &bh[0]);
                MMA16816H(o[np*2+1], ph[ks], &bh[2]);
            }
        }

        st = (st == 2) ? 0 : st + 1;
        st2 = (st2 == 2) ? 0 : st2 + 1;
    }

    // ---- epilogue: ctx = o / l -> fp16 ----
    const float i0 = 1.f / osum[0], i1 = 1.f / osum[2];
    const int rA = q0 + wid * 16 + (lane >> 2);
    const long baseA = (rowb + rA) * HH + hc;
    const long baseB = baseA + 8LL * HH;
#pragma unroll
    for (int np = 0; np < 8; np++) {
        const int col = np * 8 + t2;
        *(uint32_t*)&C16[baseA + col] =
            h2_u32(__float22half2_rn(make_float2(o[np][0] * i0, o[np][1] * i0)));
        *(uint32_t*)&C16[baseB + col] =
            h2_u32(__float22half2_rn(make_float2(o[np][2] * i1, o[np][3] * i1)));
    }
}

// ================= LayerNorm (2 rows per 512-thread block) =================
__global__ __launch_bounds__(512)
void ln_kernel(const float* __restrict__ Hin, const float* __restrict__ w,
               const float* __restrict__ bv, float* __restrict__ out)
{
    __shared__ float red[2][2][8];
    const int half = threadIdx.x >> 8;            // 0 or 1: which row
    const int tid = threadIdx.x & 255;
    const int row = blockIdx.x * 2 + half;
    const float4* xp = (const float4*)(Hin + (size_t)row * HH);
    float4 v = xp[tid];
    float s = v.x + v.y + v.z + v.w;
    float sq = v.x * v.x + v.y * v.y + v.z * v.z + v.w * v.w;
#pragma unroll
    for (int m = 16; m >= 1; m >>= 1) {
        s += __shfl_xor_sync(0xffffffffu, s, m);
        sq += __shfl_xor_sync(0xffffffffu, sq, m);
    }
    const int wid = tid >> 5, lid = tid & 31;
    if (lid == 0) { red[half][0][wid] = s; red[half][1][wid] = sq; }
    __syncthreads();
    if (wid == 0) {
        float a = (lid < 8) ? red[half][0][lid] : 0.f;
        float b = (lid < 8) ? red[half][1][lid] : 0.f;
#pragma unroll
        for (int m = 4; m >= 1; m >>= 1) {
            a += __shfl_xor_sync(0xffffffffu, a, m);
            b += __shfl_xor_sync(0xffffffffu, b, m);
        }
        if (lid == 0) { red[half][0][0] = a; red[half][1][0] = b; }
    }
    __syncthreads();
    const float mean = red[half][0][0] * (1.f / HH);
    const float var = red[half][1][0] * (1.f / HH) - mean * mean;
    const float rstd = rsqrtf(var + 1e-12f);

    const float4 wv = ((const float4*)w)[tid];
    const float4 bb = ((const float4*)bv)[tid];
    float4 o;
    o.x = wv.x * (v.x - mean) * rstd + bb.x;
    o.y = wv.y * (v.y - mean) * rstd + bb.y;
    o.z = wv.z * (v.z - mean) * rstd + bb.z;
    o.w = wv.w * (v.w - mean) * rstd + bb.w;
    ((float4*)(out + (size_t)row * HH))[tid] = o;
}

// ================= launch =================
extern "C" void kernel_launch(void* const* d_in, const int* in_sizes, int n_in,
                              void* d_out, int out_size)
{
    const float* x    = (const float*)d_in[0];
    const float* mask = (const float*)d_in[1];
    const float* Wq   = (const float*)d_in[2];
    const float* bq   = (const float*)d_in[3];
    const float* Wk   = (const float*)d_in[4];
    const float* bk   = (const float*)d_in[5];
    const float* Wv   = (const float*)d_in[6];
    const float* bv   = (const float*)d_in[7];
    const float* Wo   = (const float*)d_in[8];
    const float* bo   = (const float*)d_in[9];
    const float* lnw  = (const float*)d_in[10];
    const float* lnb  = (const float*)d_in[11];
    float* out = (float*)d_out;

    float* hbuf;
    cudaGetSymbolAddress((void**)&hbuf, g_h);
    __half *x16, *q16, *k16, *v16, *c16, *wq16, *wk16, *wv16, *wo16;
    cudaGetSymbolAddress((void**)&x16, g_x16);
    cudaGetSymbolAddress((void**)&q16, g_q16);
    cudaGetSymbolAddress((void**)&k16, g_k16);
    cudaGetSymbolAddress((void**)&v16, g_v16);
    cudaGetSymbolAddress((void**)&c16, g_c16);
    cudaGetSymbolAddress((void**)&wq16, g_wq16);
    cudaGetSymbolAddress((void**)&wk16, g_wk16);
    cudaGetSymbolAddress((void**)&wv16, g_wv16);
    cudaGetSymbolAddress((void**)&wo16, g_wo16);

    cudaFuncSetAttribute(gemm_qkv, cudaFuncAttributeMaxDynamicSharedMemorySize, GSMEM);
    cudaFuncSetAttribute(gemm_out, cudaFuncAttributeMaxDynamicSharedMemorySize, GSMEM);
    cudaFuncSetAttribute(attn_mma, cudaFuncAttributeMaxDynamicSharedMemorySize, ASMEM);

    const int n4x = MM * HH / 4;
    const int n4w = HH * HH / 4;

    // one fused cast launch: x + 4 weight matrices
    CastAll CA;
    CA.in[0] = x;  CA.out[0] = x16;  CA.n4[0] = n4x;
    CA.in[1] = Wq; CA.out[1] = wq16; CA.n4[1] = n4w;
    CA.in[2] = Wk; CA.out[2] = wk16; CA.n4[2] = n4w;
    CA.in[3] = Wv; CA.out[3] = wv16; CA.n4[3] = n4w;
    CA.in[4] = Wo; CA.out[4] = wo16; CA.n4[4] = n4w;
    dim3 cgrid(n4x / 256, 5);
    castall_kernel<<<cgrid, 256>>>(CA);

    // fused QKV projections (Q pre-scaled by log2e/8)
    QKVParams P;
    P.w[0] = wq16; P.bias[0] = bq; P.o[0] = q16;
    P.w[1] = wk16; P.bias[1] = bk; P.o[1] = k16;
    P.w[2] = wv16; P.bias[2] = bv; P.o[2] = v16;
    dim3 qkvgrid(HH / 128, MM / 128, 3);   // (8, 64, 3)
    gemm_qkv<<<qkvgrid, 256, GSMEM>>>(x16, P);

    // fp16 flash attention (static-max) -> ctx fp16
    dim3 agrid(SS / 128, NHH, BB);
    attn_mma<<<agrid, 256, ASMEM>>>(q16, k16, v16, mask, c16);

    // output projection + residual -> fp32 h
    dim3 ggrid(HH / 128, MM / 128);        // (8, 64)
    gemm_out<<<ggrid, 256, GSMEM>>>(c16, wo16, bo, x, hbuf);

    ln_kernel<<<MM / 2, 512>>>(hbuf, lnw, lnb, out);
}

// round 16
// speedup vs baseline: 1.5966x; 1.2340x over previous
#include <cuda_runtime.h>
#include <cuda_bf16.h>
#include <cuda_fp16.h>
#include <math.h>
#include <stdint.h>

#define BB 4
#define SS 2048
#define HH 1024
#define NHH 16
#define HD 64
#define MM (BB*SS)   // 8192
#define LOG2E 1.4426950408889634f
#define SMAX 8.0f    // static softmax shift (log2 domain)

// ---------------- scratch (no allocation allowed) ----------------
__device__ float g_h[MM*HH];
__device__ __half g_x16[MM*HH];
__device__ __half g_q16[MM*HH];
__device__ __half g_k16[MM*HH];
__device__ __half g_v16[MM*HH];
__device__ __half g_c16[MM*HH];
__device__ __half g_wq16[HH*HH];
__device__ __half g_wk16[HH*HH];
__device__ __half g_wv16[HH*HH];
__device__ __half g_wo16[HH*HH];

// ================= PTX helpers (baseline ISA: sm_80 features only) =================
__device__ __forceinline__ uint32_t smem_u32(const void* p) {
    uint32_t a;
    asm("{ .reg .u64 t; cvta.to.shared.u64 t, %1; cvt.u32.u64 %0, t; }" : "=r"(a) : "l"(p));
    return a;
}

#define CP_ASYNC16(dst, src) \
    asm volatile("cp.async.cg.shared.global [%0], [%1], 16;" :: "r"(dst), "l"(src) : "memory")
#define CP_ASYNC4(dst, src) \
    asm volatile("cp.async.ca.shared.global [%0], [%1], 4;" :: "r"(dst), "l"(src) : "memory")
#define CP_COMMIT() asm volatile("cp.async.commit_group;" ::: "memory")
#define CP_WAIT2()  asm volatile("cp.async.wait_group 2;" ::: "memory")
#define CP_WAIT1()  asm volatile("cp.async.wait_group 1;" ::: "memory")
#define CP_WAIT0()  asm volatile("cp.async.wait_group 0;" ::: "memory")

#define LDSM4(r0, r1, r2, r3, addr) \
    asm volatile("ldmatrix.sync.aligned.m8n8.x4.shared.b16 {%0,%1,%2,%3}, [%4];" \
        : "=r"(r0), "=r"(r1), "=r"(r2), "=r"(r3) : "r"(addr))
#define LDSM4T(r0, r1, r2, r3, addr) \
    asm volatile("ldmatrix.sync.aligned.m8n8.x4.trans.shared.b16 {%0,%1,%2,%3}, [%4];" \
        : "=r"(r0), "=r"(r1), "=r"(r2), "=r"(r3) : "r"(addr))

#define MMA16816H(d, a, b) \
    asm volatile("mma.sync.aligned.m16n8k16.row.col.f32.f16.f16.f32 " \
        "{%0,%1,%2,%3}, {%4,%5,%6,%7}, {%8,%9}, {%0,%1,%2,%3};" \
        : "+f"((d)[0]), "+f"((d)[1]), "+f"((d)[2]), "+f"((d)[3]) \
        : "r"((a)[0]), "r"((a)[1]), "r"((a)[2]), "r"((a)[3]), "r"((b)[0]), "r"((b)[1]))

__device__ __forceinline__ uint32_t h2_u32(__half2 v) { return *(uint32_t*)&v; }

// ================= cast fp32 -> fp16 =================
__device__ __forceinline__ void cast_body(const float* __restrict__ in,
                                          __half* __restrict__ out, int i)
{
    float4 v = ((const float4*)in)[i];
    ((uint2*)out)[i] = make_uint2(h2_u32(__float22half2_rn(make_float2(v.x, v.y))),
                                  h2_u32(__float22half2_rn(make_float2(v.z, v.w))));
}

__global__ __launch_bounds__(256)
void cast_kernel(const float* __restrict__ in, __half* __restrict__ out, int n4)
{
    int i = blockIdx.x * blockDim.x + threadIdx.x;
    if (i >= n4) return;
    cast_body(in, out, i);
}

struct WCast {
    const float* in[4];
    __half* out[4];
};

__global__ __launch_bounds__(256)
void cast4_kernel(WCast P, int n4)
{
    int i = blockIdx.x * blockDim.x + threadIdx.x;
    if (i >= n4) return;
    cast_body(P.in[blockIdx.y], P.out[blockIdx.y], i);
}

// ================= fp16 GEMM: C = A @ W^T + bias (fp32 accum) =================
#define GNCHUNK 16           // 1024 / 64
#define GROWB 144            // 128B data + 16B pad
#define GMATB (128 * GROWB)  // 18432
#define GSTG (2 * GMATB)     // 36864 (A, B)
#define GSMEM (2 * GSTG)     // 73728

__device__ __forceinline__
void gemm_body(const __half* __restrict__ A16, const __half* __restrict__ B16,
               const float* __restrict__ bias, const float* __restrict__ resid,
               float* __restrict__ Cf, __half* __restrict__ O16,
               float oscale, uint32_t sbase)
{
    const int tid = threadIdx.x;
    const int wid = tid >> 5, lane = tid & 31;
    const int warp_m = wid & 1, warp_n = wid >> 1;
    const int r0 = blockIdx.y * 128, c0 = blockIdx.x * 128;

    float acc[4][4][4];
#pragma unroll
    for (int i = 0; i < 4; i++)
#pragma unroll
        for (int j = 0; j < 4; j++)
#pragma unroll
            for (int q = 0; q < 4; q++) acc[i][j][q] = 0.f;

#define G_LOAD_CHUNK(c, s) do { \
    const uint32_t st = sbase + (s) * GSTG; \
    const long ka = (long)(c) * 64; \
    _Pragma("unroll") \
    for (int i_ = 0; i_ < 4; i_++) { \
        int idx = tid + 256 * i_; \
        int row = idx >> 3, u = idx & 7; \
        CP_ASYNC16(st + row * GROWB + u * 16, A16 + (long)(r0 + row) * HH + ka + u * 8); \
        CP_ASYNC16(st + GMATB + row * GROWB + u * 16, B16 + (long)(c0 + row) * HH + ka + u * 8); \
    } \
    CP_COMMIT(); \
} while (0)

    G_LOAD_CHUNK(0, 0);

    const int sub = lane >> 3, lr = lane & 7;

#pragma unroll 1
    for (int c = 0; c < GNCHUNK; c++) {
        if (c + 1 < GNCHUNK) {
            G_LOAD_CHUNK(c + 1, (c + 1) & 1);
            CP_WAIT1();
        } else {
            CP_WAIT0();
        }
        __syncthreads();

        const uint32_t a_b = sbase + (c & 1) * GSTG;
        const uint32_t b_b = a_b + GMATB;

#pragma unroll
        for (int ks = 0; ks < 4; ks++) {
            uint32_t af[4][4], bf[2][4];
            const int aunit = ks * 2 + (sub >> 1);
#pragma unroll
            for (int mf = 0; mf < 4; mf++) {
                const int arow = warp_m * 64 + mf * 16 + (sub & 1) * 8 + lr;
                LDSM4(af[mf][0], af[mf][1], af[mf][2], af[mf][3],
                      a_b + arow * GROWB + aunit * 16);
            }
            const int bunit = ks * 2 + (sub & 1);
#pragma unroll
            for (int pr = 0; pr < 2; pr++) {
                const int brow = warp_n * 32 + pr * 16 + (sub >> 1) * 8 + lr;
                LDSM4(bf[pr][0], bf[pr][1], bf[pr][2], bf[pr][3],
                      b_b + brow * GROWB + bunit * 16);
            }
#pragma unroll
            for (int mf = 0; mf < 4; mf++)
#pragma unroll
                for (int nf = 0; nf < 4; nf++)
                    MMA16816H(acc[mf][nf], af[mf], &bf[nf >> 1][(nf & 1) * 2]);
        }
        __syncthreads();
    }

    const int g = lane >> 2, t4 = lane & 3;
#pragma unroll
    for (int mf = 0; mf < 4; mf++) {
#pragma unroll
        for (int nf = 0; nf < 4; nf++) {
            const int col = c0 + warp_n * 32 + nf * 8 + 2 * t4;
            const int rowA = r0 + warp_m * 64 + mf * 16 + g;
            const int rowB = rowA + 8;
            float v0 = acc[mf][nf][0] + bias[col];
            float v1 = acc[mf][nf][1] + bias[col + 1];
            float v2 = acc[mf][nf][2] + bias[col];
            float v3 = acc[mf][nf][3] + bias[col + 1];
            if (O16) {
                v0 *= oscale; v1 *= oscale; v2 *= oscale; v3 *= oscale;
                *(uint32_t*)&O16[(long)rowA * HH + col] =
                    h2_u32(__float22half2_rn(make_float2(v0, v1)));
                *(uint32_t*)&O16[(long)rowB * HH + col] =
                    h2_u32(__float22half2_rn(make_float2(v2, v3)));
            } else {
                if (resid) {
                    const float2 ra = *(const float2*)&resid[(long)rowA * HH + col];
                    const float2 rb = *(const float2*)&resid[(long)rowB * HH + col];
                    v0 += ra.x; v1 += ra.y; v2 += rb.x; v3 += rb.y;
                }
                *(float2*)&Cf[(long)rowA * HH + col] = make_float2(v0, v1);
                *(float2*)&Cf[(long)rowB * HH + col] = make_float2(v2, v3);
            }
        }
    }
}

struct QKVParams {
    const __half* w[3];
    const float* bias[3];
    __half* o[3];
};

__global__ __launch_bounds__(256)
void gemm_qkv(const __half* __restrict__ A16, QKVParams P)
{
    extern __shared__ char smem[];
    const int z = blockIdx.z;
    gemm_body(A16, P.w[z], P.bias[z], nullptr, nullptr, P.o[z],
              (z == 0) ? (0.125f * LOG2E) : 1.0f, smem_u32(smem));
}

__global__ __launch_bounds__(256)
void gemm_out(const __half* __restrict__ A16, const __half* __restrict__ B16,
              const float* __restrict__ bias, const float* __restrict__ resid,
              float* __restrict__ Cf)
{
    extern __shared__ char smem[];
    gemm_body(A16, B16, bias, resid, Cf, nullptr, 1.0f, smem_u32(smem));
}

// ================= fp16 tensor-core flash attention (static-max softmax) =================
#define NT (SS / 64)            // 32 tiles
#define AQTB 16384              // Q tile: 128 rows x 128B
#define AKTB 8192               // 64 rows x 128B
#define AKVSTG (2 * AKTB)       // K, V per stage
#define ASMEM (AQTB + 3*AKVSTG + 3*256 + 256)   // 66560

__device__ __forceinline__ uint32_t swz(int row, int unit) {
    return (uint32_t)(row * 128 + ((unit ^ (row & 7)) * 16));
}

__global__ __launch_bounds__(256, 2)
void attn_mma(const __half* __restrict__ Q16, const __half* __restrict__ K16,
              const __half* __restrict__ V16, const float* __restrict__ mask,
              __half* __restrict__ C16)
{
    extern __shared__ char smem[];
    const uint32_t sb = smem_u32(smem);
    const int tid = threadIdx.x, wid = tid >> 5, lane = tid & 31;
    const int sub = lane >> 3, lr = lane & 7;
    const int b = blockIdx.z, h = blockIdx.y;
    const int q0 = blockIdx.x * 128;
    const long rowb = (long)b * SS;
    const int hc = h * 64;

    const uint32_t s_q = sb;
    const uint32_t s_kv = sb + AQTB;
    const uint32_t s_mk = sb + AQTB + 3 * AKVSTG;
    const char* mkp = smem + AQTB + 3 * AKVSTG;

    // ---- load Q tile (group 0) ----
#pragma unroll
    for (int i = 0; i < 4; i++) {
        int idx = tid + 256 * i;
        int row = idx >> 3, u = idx & 7;
        CP_ASYNC16(s_q + swz(row, u), Q16 + (rowb + q0 + row) * HH + hc + u * 8);
    }
    CP_COMMIT();

#define A_LOAD_KV(t, st) do { \
    const uint32_t kb_ = s_kv + (st) * AKVSTG; \
    const long k0_ = (long)(t) * 64; \
    _Pragma("unroll") \
    for (int i_ = 0; i_ < 2; i_++) { \
        int idx = tid + 256 * i_; \
        int row = idx >> 3, u = idx & 7; \
        long go = (rowb + k0_ + row) * HH + hc + u * 8; \
        uint32_t so = swz(row, u); \
        CP_ASYNC16(kb_ + so, K16 + go); \
        CP_ASYNC16(kb_ + AKTB + so, V16 + go); \
    } \
    if (tid < 64) CP_ASYNC4(s_mk + (st) * 256 + tid * 4, mask + rowb + k0_ + tid); \
    CP_COMMIT(); \
} while (0)

    A_LOAD_KV(0, 0);   // group 1
    A_LOAD_KV(1, 1);   // group 2

    // ---- hoist Q fragments (loop-invariant across all KV tiles) ----
    CP_WAIT2();        // Q (group 0) complete
    __syncthreads();
    uint32_t qf[4][4];
    {
        const int arow = wid * 16 + (sub & 1) * 8 + lr;
#pragma unroll
        for (int ks = 0; ks < 4; ks++)
            LDSM4(qf[ks][0], qf[ks][1], qf[ks][2], qf[ks][3],
                  s_q + swz(arow, ks * 2 + (sub >> 1)));
    }

    float o[8][4];
#pragma unroll
    for (int i = 0; i < 8; i++)
#pragma unroll
        for (int j = 0; j < 4; j++) o[i][j] = 0.f;
    float osum[4] = {0.f, 0.f, 0.f, 0.f};   // row-sum (l) via ones-MMA; never rescaled
    uint32_t ones2[2];
    ones2[0] = 0x3C003C00u; ones2[1] = 0x3C003C00u;  // fp16 1.0 x4

    const int t2 = (lane & 3) * 2;
    int st = 0;       // stage of tile t
    int st2 = 2;      // stage of tile t+2

#pragma unroll 1
    for (int t = 0; t < NT; t++) {
        if (t + 2 < NT) CP_WAIT1(); else CP_WAIT0();
        __syncthreads();
        if (t + 2 < NT) A_LOAD_KV(t + 2, st2);
        const uint32_t kb = s_kv + st * AKVSTG;

        // ---- S_log2 = (Q*scale*log2e) @ K^T (fp16): 128x64 ----
        float s[8][4];
#pragma unroll
        for (int i = 0; i < 8; i++)
#pragma unroll
            for (int j = 0; j < 4; j++) s[i][j] = 0.f;

#pragma unroll
        for (int ks = 0; ks < 4; ks++) {
#pragma unroll
            for (int np = 0; np < 4; np++) {
                uint32_t bh[4];
                const int brow = np * 16 + (sub >> 1) * 8 + lr;
                LDSM4(bh[0], bh[1], bh[2], bh[3], kb + swz(brow, ks * 2 + (sub & 1)));
                MMA16816H(s[np*2],   qf[ks], &bh[0]);
                MMA16816H(s[np*2+1], qf[ks], &bh[2]);
            }
        }

        // ---- P = exp2(s + mask*log2e - SMAX) in fp16x2; no max reduction ----
        uint32_t ph[4][4];
#pragma unroll
        for (int ks = 0; ks < 4; ks++) {
            const float2 mvA = *(const float2*)(mkp + st * 256 + ((2*ks)   * 8 + t2) * 4);
            const float2 mvB = *(const float2*)(mkp + st * 256 + ((2*ks+1) * 8 + t2) * 4);
            const float cA0 = fmaf(mvA.x, LOG2E, -SMAX), cA1 = fmaf(mvA.y, LOG2E, -SMAX);
            const float cB0 = fmaf(mvB.x, LOG2E, -SMAX), cB1 = fmaf(mvB.y, LOG2E, -SMAX);
            ph[ks][0] = h2_u32(h2exp2(__floats2half2_rn(s[2*ks][0]   + cA0, s[2*ks][1]   + cA1)));
            ph[ks][1] = h2_u32(h2exp2(__floats2half2_rn(s[2*ks][2]   + cA0, s[2*ks][3]   + cA1)));
            ph[ks][2] = h2_u32(h2exp2(__floats2half2_rn(s[2*ks+1][0] + cB0, s[2*ks+1][1] + cB1)));
            ph[ks][3] = h2_u32(h2exp2(__floats2half2_rn(s[2*ks+1][2] + cB0, s[2*ks+1][3] + cB1)));
        }

        // ---- O += P @ V ; l += P @ 1 (both on tensor pipe, no rescale) ----
        const uint32_t vb = kb + AKTB;
#pragma unroll
        for (int ks = 0; ks < 4; ks++) {
            MMA16816H(osum, ph[ks], ones2);
#pragma unroll
            for (int np = 0; np < 4; np++) {
                uint32_t bh[4];
                const int vrow = ks * 16 + (sub & 1) * 8 + lr;
                LDSM4T(bh[0], bh[1], bh[2], bh[3], vb + swz(vrow, np * 2 + (sub >> 1)));
                MMA16816H(o[np*2],   ph[ks], &bh[0]);
                MMA16816H(o[np*2+1], ph[ks], &bh[2]);
            }
        }

        st = (st == 2) ? 0 : st + 1;
        st2 = (st2 == 2) ? 0 : st2 + 1;
    }

    // ---- epilogue: ctx = o / l -> fp16 ----
    const float i0 = 1.f / osum[0], i1 = 1.f / osum[2];
    const int rA = q0 + wid * 16 + (lane >> 2);
    const long baseA = (rowb + rA) * HH + hc;
    const long baseB = baseA + 8LL * HH;
#pragma unroll
    for (int np = 0; np < 8; np++) {
        const int col = np * 8 + t2;
        *(uint32_t*)&C16[baseA + col] =
            h2_u32(__float22half2_rn(make_float2(o[np][0] * i0, o[np][1] * i0)));
        *(uint32_t*)&C16[baseB + col] =
            h2_u32(__float22half2_rn(make_float2(o[np][2] * i1, o[np][3] * i1)));
    }
}

// ================= LayerNorm =================
__global__ __launch_bounds__(256)
void ln_kernel(const float* __restrict__ Hin, const float* __restrict__ w,
               const float* __restrict__ bv, float* __restrict__ out)
{
    __shared__ float red[2][8];
    int row = blockIdx.x;
    int tid = threadIdx.x;
    const float4* xp = (const float4*)(Hin + (size_t)row * HH);
    float4 v = xp[tid];
    float s = v.x + v.y + v.z + v.w;
    float sq = v.x * v.x + v.y * v.y + v.z * v.z + v.w * v.w;
#pragma unroll
    for (int m = 16; m >= 1; m >>= 1) {
        s += __shfl_xor_sync(0xffffffffu, s, m);
        sq += __shfl_xor_sync(0xffffffffu, sq, m);
    }
    int wid = tid >> 5, lid = tid & 31;
    if (lid == 0) { red[0][wid] = s; red[1][wid] = sq; }
    __syncthreads();
    if (wid == 0) {
        float a = (lid < 8) ? red[0][lid] : 0.f;
        float b = (lid < 8) ? red[1][lid] : 0.f;
#pragma unroll
        for (int m = 4; m >= 1; m >>= 1) {
            a += __shfl_xor_sync(0xffffffffu, a, m);
            b += __shfl_xor_sync(0xffffffffu, b, m);
        }
        if (lid == 0) { red[0][0] = a; red[1][0] = b; }
    }
    __syncthreads();
    float mean = red[0][0] * (1.f / HH);
    float var = red[1][0] * (1.f / HH) - mean * mean;
    float rstd = rsqrtf(var + 1e-12f);

    const float4 wv = ((const float4*)w)[tid];
    const float4 bb = ((const float4*)bv)[tid];
    float4 o;
    o.x = wv.x * (v.x - mean) * rstd + bb.x;
    o.y = wv.y * (v.y - mean) * rstd + bb.y;
    o.z = wv.z * (v.z - mean) * rstd + bb.z;
    o.w = wv.w * (v.w - mean) * rstd + bb.w;
    ((float4*)(out + (size_t)row * HH))[tid] = o;
}

// ================= launch =================
extern "C" void kernel_launch(void* const* d_in, const int* in_sizes, int n_in,
                              void* d_out, int out_size)
{
    const float* x    = (const float*)d_in[0];
    const float* mask = (const float*)d_in[1];
    const float* Wq   = (const float*)d_in[2];
    const float* bq   = (const float*)d_in[3];
    const float* Wk   = (const float*)d_in[4];
    const float* bk   = (const float*)d_in[5];
    const float* Wv   = (const float*)d_in[6];
    const float* bv   = (const float*)d_in[7];
    const float* Wo   = (const float*)d_in[8];
    const float* bo   = (const float*)d_in[9];
    const float* lnw  = (const float*)d_in[10];
    const float* lnb  = (const float*)d_in[11];
    float* out = (float*)d_out;

    float* hbuf;
    cudaGetSymbolAddress((void**)&hbuf, g_h);
    __half *x16, *q16, *k16, *v16, *c16, *wq16, *wk16, *wv16, *wo16;
    cudaGetSymbolAddress((void**)&x16, g_x16);
    cudaGetSymbolAddress((void**)&q16, g_q16);
    cudaGetSymbolAddress((void**)&k16, g_k16);
    cudaGetSymbolAddress((void**)&v16, g_v16);
    cudaGetSymbolAddress((void**)&c16, g_c16);
    cudaGetSymbolAddress((void**)&wq16, g_wq16);
    cudaGetSymbolAddress((void**)&wk16, g_wk16);
    cudaGetSymbolAddress((void**)&wv16, g_wv16);
    cudaGetSymbolAddress((void**)&wo16, g_wo16);

    cudaFuncSetAttribute(gemm_qkv, cudaFuncAttributeMaxDynamicSharedMemorySize, GSMEM);
    cudaFuncSetAttribute(gemm_out, cudaFuncAttributeMaxDynamicSharedMemorySize, GSMEM);
    cudaFuncSetAttribute(attn_mma, cudaFuncAttributeMaxDynamicSharedMemorySize, ASMEM);

    const int n4x = MM * HH / 4;
    const int n4w = HH * HH / 4;
    cast_kernel<<<n4x / 256, 256>>>(x, x16, n4x);

    WCast WC;
    WC.in[0] = Wq; WC.out[0] = wq16;
    WC.in[1] = Wk; WC.out[1] = wk16;
    WC.in[2] = Wv; WC.out[2] = wv16;
    WC.in[3] = Wo; WC.out[3] = wo16;
    dim3 wcgrid(n4w / 256, 4);
    cast4_kernel<<<wcgrid, 256>>>(WC, n4w);

    // fused QKV projections (Q pre-scaled by log2e/8)
    QKVParams P;
    P.w[0] = wq16; P.bias[0] = bq; P.o[0] = q16;
    P.w[1] = wk16; P.bias[1] = bk; P.o[1] = k16;
    P.w[2] = wv16; P.bias[2] = bv; P.o[2] = v16;
    dim3 qkvgrid(HH / 128, MM / 128, 3);
    gemm_qkv<<<qkvgrid, 256, GSMEM>>>(x16, P);

    // fp16 flash attention (static-max) -> ctx fp16
    dim3 agrid(SS / 128, NHH, BB);
    attn_mma<<<agrid, 256, ASMEM>>>(q16, k16, v16, mask, c16);

    // output projection + residual -> fp32 h
    dim3 ggrid(HH / 128, MM / 128);
    gemm_out<<<ggrid, 256, GSMEM>>>(c16, wo16, bo, x, hbuf);

    ln_kernel<<<MM, 256>>>(hbuf, lnw, lnb, out);
}